// round 17
// baseline (speedup 1.0000x reference)
#include <cuda_runtime.h>
#include <cuda_fp16.h>
#include <cstdint>
#include <cstddef>

#define BB 8
#define NN 2048
#define DD 128

// ---------------- scratch (no allocs allowed) ----------------
__device__ __half g_a16[(size_t)BB * NN * NN];   // 67MB frag-packed fp16 A
__device__ __half g_zpk[BB * NN * DD];           // 4MB packed fp16 Z
__device__ __half g_w16[3 * DD * DD];            // 96KB packed fp16 W (3 layers)
__device__ float  g_part[2 * BB * NN * DD];      // split-K partials (16MB)
__device__ float  g_rs  [BB * NN];               // full rowsums (layer 0)
__device__ float  g_invden[BB * NN];

typedef unsigned long long u64;

// ---------------- PTX helpers ----------------
__device__ __forceinline__ uint32_t smem_u32(const void* p) {
    uint32_t a;
    asm("{ .reg .u64 t; cvta.to.shared.u64 t, %1; cvt.u32.u64 %0, t; }" : "=r"(a) : "l"(p));
    return a;
}
__device__ __forceinline__ void cp16(uint32_t dst, const void* src) {
    asm volatile("cp.async.cg.shared.global [%0], [%1], 16;" :: "r"(dst), "l"(src));
}
__device__ __forceinline__ void cp_commit() {
    asm volatile("cp.async.commit_group;" ::: "memory");
}
__device__ __forceinline__ uint32_t pkh(float lo, float hi) {
    uint32_t d;
    asm("cvt.rn.f16x2.f32 %0, %1, %2;" : "=r"(d) : "f"(hi), "f"(lo));
    return d;
}
__device__ __forceinline__ void mma_f16(float* d,
    uint32_t a0, uint32_t a1, uint32_t a2, uint32_t a3, uint32_t b0, uint32_t b1)
{
    asm volatile(
        "mma.sync.aligned.m16n8k16.row.col.f32.f16.f16.f32 "
        "{%0,%1,%2,%3}, {%4,%5,%6,%7}, {%8,%9}, {%0,%1,%2,%3};"
        : "+f"(d[0]), "+f"(d[1]), "+f"(d[2]), "+f"(d[3])
        : "r"(a0), "r"(a1), "r"(a2), "r"(a3), "r"(b0), "r"(b1));
}

// =================================================================
//  Layouts
//  A16 [b][ks16][row][16 halves]: half p = c*4+h*2+e holds kl = 2c+8h+e.
//  Zpk/W16 [kp][n][32 halves]: half = c*8 + ks*4 + h*2 + e, kl = 2c+8h+e.
// =================================================================

// pack 16 consecutive k-values (4 float4s) into A16 16-half order
__device__ __forceinline__ void pack16(uint4& w0, uint4& w1,
    float4 v0, float4 v1, float4 v2, float4 v3)
{
    w0.x = pkh(v0.x, v0.y);  w0.y = pkh(v2.x, v2.y);
    w0.z = pkh(v0.z, v0.w);  w0.w = pkh(v2.z, v2.w);
    w1.x = pkh(v1.x, v1.y);  w1.y = pkh(v3.x, v3.y);
    w1.z = pkh(v1.z, v1.w);  w1.w = pkh(v3.z, v3.w);
}

// =================================================================
//  wpack: W fp32 [k][n] -> W16 packed fp16 (Zpk layout), 3 layers.
//  grid 12 = 3 layers x 4 kp blocks, 256 threads.
// =================================================================
__global__ void wpack(const float* __restrict__ W, __half* __restrict__ W16)
{
    const int layer = blockIdx.x >> 2, kp = blockIdx.x & 3;
    const float* w = W + layer * DD * DD;
    __half* dst = W16 + layer * DD * DD;
    for (int idx = threadIdx.x; idx < 4096; idx += 256) {
        const int kl32 = idx >> 7, n = idx & 127;
        const int k = kp * 32 + kl32;
        const int ks = (kl32 >> 4) & 1, kl = kl32 & 15;
        const int e = kl & 1, xx = kl >> 1;
        const int cc = xx & 3, hh = xx >> 2;
        dst[kp * 4096 + n * 32 + cc * 8 + ks * 4 + hh * 2 + e] =
            __float2half(w[k * DD + n]);
    }
}

// =================================================================
//  a2h: streaming convert A fp32 -> frag-packed A16 + full rowsums.
// =================================================================
__global__ __launch_bounds__(256, 4) void a2h(
    const float* __restrict__ A,
    __half* __restrict__ A16,
    float* __restrict__ rsOut)
{
    __shared__ __align__(16) float sbuf[3][32][132];
    __shared__ float red[8][32];

    const int tid = threadIdx.x;
    const int b = blockIdx.y, row0 = blockIdx.x * 32;

    const int lrow = tid >> 3, lj = tid & 7;
    const float* src = A + ((size_t)b * NN + row0 + lrow) * NN + lj * 16;

    auto load = [&](int i) {
        const uint32_t d = smem_u32(&sbuf[i % 3][lrow][lj * 16]);
        const float* s = src + i * 128;
        cp16(d, s);  cp16(d + 16, s + 4);  cp16(d + 32, s + 8);  cp16(d + 48, s + 12);
        cp_commit();
    };

    const int ks = tid >> 5, row = tid & 31;
    float rsum = 0.f;

    load(0);
    load(1);

    #pragma unroll 1
    for (int i = 0; i < 16; i++) {
        if (i < 14) { asm volatile("cp.async.wait_group 1;" ::: "memory"); }
        else        { asm volatile("cp.async.wait_group 0;" ::: "memory"); }
        __syncthreads();
        if (i < 14) load(i + 2);

        const float* r = &sbuf[i % 3][row][ks * 16];
        float4 v0 = reinterpret_cast<const float4*>(r)[0];
        float4 v1 = reinterpret_cast<const float4*>(r)[1];
        float4 v2 = reinterpret_cast<const float4*>(r)[2];
        float4 v3 = reinterpret_cast<const float4*>(r)[3];
        rsum += (v0.x + v0.y + v0.z + v0.w) + (v1.x + v1.y + v1.z + v1.w)
              + (v2.x + v2.y + v2.z + v2.w) + (v3.x + v3.y + v3.z + v3.w);
        uint4 w0, w1;
        pack16(w0, w1, v0, v1, v2, v3);
        uint4* dst = reinterpret_cast<uint4*>(
            A16 + ((size_t)(b * 128 + i * 8 + ks) * NN + row0 + row) * 16);
        dst[0] = w0;  dst[1] = w1;
    }

    red[ks][row] = rsum;
    __syncthreads();
    if (tid < 32) {
        float s = 0.f;
        #pragma unroll
        for (int q = 0; q < 8; q++) s += red[q][tid];
        rsOut[(size_t)b * NN + row0 + tid] = s;
    }
}

// =================================================================
//  ax_direct: A16 @ Z, fragments loaded directly from global.
//  CTA 128x128, 8 warps (4Mx2N, 32x64 tiles), split-K x2.
// =================================================================
__global__ __launch_bounds__(256, 2) void ax_direct(
    const __half* __restrict__ A16, const __half* __restrict__ Zp,
    float* __restrict__ Pout)
{
    const int tid = threadIdx.x, lane = tid & 31, wid = tid >> 5;
    const int b = blockIdx.y, z = blockIdx.z, m0 = blockIdx.x * 128;
    const int g = lane >> 2, c = lane & 3;
    const int wm = (wid & 3) * 32, wn = (wid >> 2) * 64;

    const __half* aBase = A16 + (size_t)(b * 128 + z * 64) * ((size_t)NN * 16)
                        + (size_t)(m0 + wm + g) * 16 + c * 4;
    const __half* zBase = Zp + (size_t)b * NN * DD + (size_t)(z * 32) * 4096
                        + (wn + g) * 32 + c * 8;

    float acc[2][8][4];
    #pragma unroll
    for (int mi = 0; mi < 2; mi++)
        #pragma unroll
        for (int nj = 0; nj < 8; nj++)
            #pragma unroll
            for (int q = 0; q < 4; q++) acc[mi][nj][q] = 0.f;

    #pragma unroll 1
    for (int kp = 0; kp < 32; kp++) {
        const __half* a0p = aBase + (size_t)(2 * kp) * ((size_t)NN * 16);
        const __half* a1p = a0p + (size_t)NN * 16;
        uint2 u00 = *reinterpret_cast<const uint2*>(a0p);
        uint2 v00 = *reinterpret_cast<const uint2*>(a0p + 8 * 16);
        uint2 u01 = *reinterpret_cast<const uint2*>(a0p + 16 * 16);
        uint2 v01 = *reinterpret_cast<const uint2*>(a0p + 24 * 16);
        uint2 u10 = *reinterpret_cast<const uint2*>(a1p);
        uint2 v10 = *reinterpret_cast<const uint2*>(a1p + 8 * 16);
        uint2 u11 = *reinterpret_cast<const uint2*>(a1p + 16 * 16);
        uint2 v11 = *reinterpret_cast<const uint2*>(a1p + 24 * 16);
        const __half* zp2 = zBase + (size_t)kp * 4096;
        uint4 bb[8];
        #pragma unroll
        for (int nj = 0; nj < 8; nj++)
            bb[nj] = *reinterpret_cast<const uint4*>(zp2 + nj * 256);

        #pragma unroll
        for (int nj = 0; nj < 8; nj++) {
            mma_f16(acc[0][nj], u00.x, v00.x, u00.y, v00.y, bb[nj].x, bb[nj].y);
            mma_f16(acc[1][nj], u01.x, v01.x, u01.y, v01.y, bb[nj].x, bb[nj].y);
            mma_f16(acc[0][nj], u10.x, v10.x, u10.y, v10.y, bb[nj].z, bb[nj].w);
            mma_f16(acc[1][nj], u11.x, v11.x, u11.y, v11.y, bb[nj].z, bb[nj].w);
        }
    }

    float* pb = Pout + (size_t)(z * BB + b) * NN * DD;
    #pragma unroll
    for (int mi = 0; mi < 2; mi++) {
        const int r_lo = wm + 16 * mi + g;
        float* o_lo = pb + (size_t)(m0 + r_lo) * DD;
        float* o_hi = pb + (size_t)(m0 + r_lo + 8) * DD;
        #pragma unroll
        for (int nj = 0; nj < 8; nj++) {
            const int col = wn + 8 * nj + 2 * c;
            *reinterpret_cast<float2*>(o_lo + col) = make_float2(acc[mi][nj][0], acc[mi][nj][1]);
            *reinterpret_cast<float2*>(o_hi + col) = make_float2(acc[mi][nj][2], acc[mi][nj][3]);
        }
    }
}

// =================================================================
//  zpack_store: acc -> packed-Z staging buffer (16384 halves)
// =================================================================
__device__ __forceinline__ void zpack_store(
    __half* hb, const float acc[2][8][4],
    int wm, int wn, int g, int c)
{
    #pragma unroll
    for (int mi = 0; mi < 2; mi++)
        #pragma unroll
        for (int q = 0; q < 4; q++)
            #pragma unroll
            for (int nj = 0; nj < 8; nj++) {
                const int t = wm + 16 * mi + g + 8 * (q >> 1);
                const int n = wn + 8 * nj + 2 * c + (q & 1);
                const int kl = t & 15, e = kl & 1, xx = kl >> 1;
                const int idx = (t >> 5) * 4096 + n * 32
                              + (xx & 3) * 8 + ((t >> 4) & 1) * 4 + (xx >> 2) * 2 + e;
                hb[idx] = __float2half(acc[mi][nj][q]);
            }
}

// =================================================================
//  xw16: unified X@W kernel (fp16 HMMA).
//  MODE 0: x = Xin (raw fp32 input)
//  MODE 1: x = relu((p0+p1+bias)*invden), invden from rowsums (writes invd)
//  MODE 2: same but invden loaded
//  Phase 1: pack x-tile (128 tokens x 128 feats) as fp16 frags in smem.
//  Phase 2: ax_direct-style mainloop vs packed W16 (global, L1-hot).
//  Epilogue: zpack -> Zp. smem 33KB.
// =================================================================
template<int MODE>
__global__ __launch_bounds__(256) void xw16(
    const float* __restrict__ Xin,
    const float* __restrict__ part,
    const float* __restrict__ rs,
    float* __restrict__ invd,
    const float* __restrict__ bias,
    const __half* __restrict__ W16l,
    __half* __restrict__ Zp)
{
    __shared__ __align__(16) __half xs[8 * 128 * 16];   // 32KB: [ks16][row][16]

    const int tid = threadIdx.x, lane = tid & 31, wid = tid >> 5;
    const int m0 = blockIdx.x * 128;

    // ---- phase 1: build packed x tile ----
    {
        const int tr = tid >> 1, fh = (tid & 1) * 64;
        const size_t tok = (size_t)(m0 + tr);
        float4 v[16];
        if (MODE == 0) {
            const float4* xsrc = reinterpret_cast<const float4*>(Xin + tok * DD + fh);
            #pragma unroll
            for (int j = 0; j < 16; j++) v[j] = xsrc[j];
        } else {
            float inv;
            if (MODE == 1) {
                inv = 1.0f / (rs[tok] + 1.0f);
                if ((tid & 1) == 0) invd[tok] = inv;
            } else {
                inv = invd[tok];
            }
            const float4* p0 = reinterpret_cast<const float4*>(part + tok * DD + fh);
            const float4* p1 = reinterpret_cast<const float4*>(part + (size_t)BB * NN * DD + tok * DD + fh);
            #pragma unroll
            for (int j = 0; j < 16; j++) {
                float4 a = p0[j], b2 = p1[j];
                float4 bv = *reinterpret_cast<const float4*>(bias + fh + j * 4);
                v[j].x = fmaxf((a.x + b2.x + bv.x) * inv, 0.f);
                v[j].y = fmaxf((a.y + b2.y + bv.y) * inv, 0.f);
                v[j].z = fmaxf((a.z + b2.z + bv.z) * inv, 0.f);
                v[j].w = fmaxf((a.w + b2.w + bv.w) * inv, 0.f);
            }
        }
        const int ksb0 = fh >> 4;  // 0 or 4
        #pragma unroll
        for (int q = 0; q < 4; q++) {
            uint4 w0, w1;
            pack16(w0, w1, v[q * 4 + 0], v[q * 4 + 1], v[q * 4 + 2], v[q * 4 + 3]);
            uint4* d = reinterpret_cast<uint4*>(xs + ((ksb0 + q) * 128 + tr) * 16);
            d[0] = w0;  d[1] = w1;
        }
    }
    __syncthreads();

    // ---- phase 2: mainloop vs packed W ----
    const int g = lane >> 2, c = lane & 3;
    const int wm = (wid & 3) * 32, wn = (wid >> 2) * 64;
    const __half* wBase = W16l + (wn + g) * 32 + c * 8;

    float acc[2][8][4];
    #pragma unroll
    for (int mi = 0; mi < 2; mi++)
        #pragma unroll
        for (int nj = 0; nj < 8; nj++)
            #pragma unroll
            for (int q = 0; q < 4; q++) acc[mi][nj][q] = 0.f;

    #pragma unroll
    for (int kp = 0; kp < 4; kp++) {
        uint4 bb[8];
        #pragma unroll
        for (int nj = 0; nj < 8; nj++)
            bb[nj] = *reinterpret_cast<const uint4*>(wBase + kp * 4096 + nj * 256);
        uint32_t af[2][2][4];
        #pragma unroll
        for (int ks2 = 0; ks2 < 2; ks2++)
            #pragma unroll
            for (int mi = 0; mi < 2; mi++) {
                const int rlo = wm + 16 * mi + g;
                uint2 u = *reinterpret_cast<const uint2*>(xs + ((2 * kp + ks2) * 128 + rlo) * 16 + c * 4);
                uint2 v2 = *reinterpret_cast<const uint2*>(xs + ((2 * kp + ks2) * 128 + rlo + 8) * 16 + c * 4);
                af[ks2][mi][0] = u.x;  af[ks2][mi][1] = v2.x;
                af[ks2][mi][2] = u.y;  af[ks2][mi][3] = v2.y;
            }
        #pragma unroll
        for (int nj = 0; nj < 8; nj++) {
            mma_f16(acc[0][nj], af[0][0][0], af[0][0][1], af[0][0][2], af[0][0][3], bb[nj].x, bb[nj].y);
            mma_f16(acc[1][nj], af[0][1][0], af[0][1][1], af[0][1][2], af[0][1][3], bb[nj].x, bb[nj].y);
            mma_f16(acc[0][nj], af[1][0][0], af[1][0][1], af[1][0][2], af[1][0][3], bb[nj].z, bb[nj].w);
            mma_f16(acc[1][nj], af[1][1][0], af[1][1][1], af[1][1][2], af[1][1][3], bb[nj].z, bb[nj].w);
        }
    }

    // ---- epilogue: pack Z and store ----
    __syncthreads();                       // xs reads done; reuse as staging
    zpack_store(xs, acc, wm, wn, g, c);
    __syncthreads();

    const int zb = m0 >> 11, mloc = m0 & 2047;
    uint4* dst = reinterpret_cast<uint4*>(Zp + (size_t)zb * NN * DD + (size_t)(mloc >> 5) * 4096);
    const uint4* src = reinterpret_cast<const uint4*>(xs);
    #pragma unroll 1
    for (int i2 = tid; i2 < 2048; i2 += 256)
        dst[i2] = src[i2];
}

// =================================================================
//  Final reduce: out = relu((p0 + p1 + bias) * invden)
// =================================================================
__global__ __launch_bounds__(256, 8) void reduce_fin(
    const float* __restrict__ part,
    const float* __restrict__ bias,
    const float* __restrict__ invd,
    float* __restrict__ out)
{
    const size_t base = ((size_t)blockIdx.x * 256 + threadIdx.x) * 4;
    const int f0 = (int)(base & 127);
    const size_t tg = base >> 7;
    const float inv = invd[tg];

    float4 p0 = *reinterpret_cast<const float4*>(part + base);
    float4 p1 = *reinterpret_cast<const float4*>(part + (size_t)BB * NN * DD + base);
    float4 bv = *reinterpret_cast<const float4*>(bias + f0);
    float4 o;
    o.x = fmaxf((p0.x + p1.x + bv.x) * inv, 0.f);
    o.y = fmaxf((p0.y + p1.y + bv.y) * inv, 0.f);
    o.z = fmaxf((p0.z + p1.z + bv.z) * inv, 0.f);
    o.w = fmaxf((p0.w + p1.w + bv.w) * inv, 0.f);
    *reinterpret_cast<float4*>(out + base) = o;
}

// =================================================================
extern "C" void kernel_launch(void* const* d_in, const int* in_sizes, int n_in,
                              void* d_out, int out_size)
{
    const float *inputs = nullptr, *adj = nullptr, *W = nullptr, *bias = nullptr;
    for (int i = 0; i < n_in; i++) {
        const long long s = in_sizes[i];
        if      (s == (long long)BB * NN * DD) inputs = (const float*)d_in[i];
        else if (s == (long long)BB * NN * NN) adj    = (const float*)d_in[i];
        else if (s == 3LL * DD * DD)           W      = (const float*)d_in[i];
        else if (s == 3LL * DD)                bias   = (const float*)d_in[i];
    }
    float* out = (float*)d_out;

    __half *a16, *zp, *w16;
    float *part, *rsv, *invd;
    cudaGetSymbolAddress((void**)&a16,  g_a16);
    cudaGetSymbolAddress((void**)&zp,   g_zpk);
    cudaGetSymbolAddress((void**)&w16,  g_w16);
    cudaGetSymbolAddress((void**)&part, g_part);
    cudaGetSymbolAddress((void**)&rsv,  g_rs);
    cudaGetSymbolAddress((void**)&invd, g_invden);

    const dim3 gAX(NN / 128, BB, 2);          // 256 CTAs (split-K x2)
    const dim3 gA2H(NN / 32, BB);             // 512 CTAs
    const int  gZ = (BB * NN) / 128;          // 128 CTAs
    const int  gRED = (BB * NN * DD) / 1024;  // 2048 CTAs

    wpack<<<12, 256>>>(W, w16);
    // layer 0
    xw16<0><<<gZ, 256>>>(inputs, nullptr, nullptr, nullptr, nullptr, w16, zp);
    a2h<<<gA2H, 256>>>(adj, a16, rsv);
    ax_direct<<<gAX, 256>>>(a16, zp, part);
    // reduce0 + zk1
    xw16<1><<<gZ, 256>>>(nullptr, part, rsv, invd, bias, w16 + DD * DD, zp);
    // layer 1
    ax_direct<<<gAX, 256>>>(a16, zp, part);
    // reduce1 + zk2
    xw16<2><<<gZ, 256>>>(nullptr, part, nullptr, invd, bias + DD, w16 + 2 * DD * DD, zp);
    // layer 2
    ax_direct<<<gAX, 256>>>(a16, zp, part);
    reduce_fin<<<gRED, 256>>>(part, bias + 2 * DD, invd, out);
}